// round 14
// baseline (speedup 1.0000x reference)
#include <cuda_runtime.h>
#include <cstdint>

// 2x FIR upsample, depthwise separable [1,3,3,1]/4 per axis (factor=2 gain).
//   out[2i]   = 0.25*x[i-1] + 0.75*x[i]
//   out[2i+1] = 0.75*x[i]   + 0.25*x[i+1]
// Input (8,128,128,128) f32 -> Output (8,128,256,256) f32.
//
// Software-pipelined multi-tile worker:
//   each block runs T_TILES=8 tiles; TMA bulk-load (double-buffered s_in +
//   2 mbarriers) overlaps compute, TMA bulk-store (double-buffered s_out,
//   wait_group 1 backpressure) overlaps everything. Per-warp L1tex path only
//   sees conflict-free LDS/STS.

#define H_IN 128
#define W_IN 128
#define W_OUT 256
#define RPB 8                     // input rows per tile
#define IN_TROWS (RPB + 2)        // staged rows r0-1 .. r0+8
#define NTHREADS 128
#define T_TILES 8                 // tiles per block

__device__ __forceinline__ uint32_t s2u(const void* p) {
    return (uint32_t)__cvta_generic_to_shared(p);
}

__device__ __forceinline__ float4 blend(float wa, float4 a, float wb, float4 b) {
    return make_float4(wa*a.x + wb*b.x, wa*a.y + wb*b.y,
                       wa*a.z + wb*b.z, wa*a.w + wb*b.w);
}

// Horizontal 2x upsample: lane l holds cols 4l..4l+3; halo via shfl
// (zero at edges: W=128=32*4 spans the warp exactly).
__device__ __forceinline__ void hup(float4 v, int lane, float4& lo, float4& hi) {
    float left  = __shfl_up_sync(0xFFFFFFFFu, v.w, 1);
    float right = __shfl_down_sync(0xFFFFFFFFu, v.x, 1);
    if (lane == 0)  left  = 0.f;
    if (lane == 31) right = 0.f;
    lo.x = 0.25f * left + 0.75f * v.x;
    lo.y = 0.75f * v.x  + 0.25f * v.y;
    lo.z = 0.25f * v.x  + 0.75f * v.y;
    lo.w = 0.75f * v.y  + 0.25f * v.z;
    hi.x = 0.25f * v.y  + 0.75f * v.z;
    hi.y = 0.75f * v.z  + 0.25f * v.w;
    hi.z = 0.25f * v.z  + 0.75f * v.w;
    hi.w = 0.75f * v.w  + 0.25f * right;
}

__global__ __launch_bounds__(NTHREADS)
void upsample2x_fir_kernel(const float* __restrict__ x, float* __restrict__ out) {
    __shared__ __align__(16) float s_in[2][IN_TROWS * W_IN];   // 2 x 5120 B
    __shared__ __align__(16) float s_out[2][2 * RPB * W_OUT];  // 2 x 16384 B
    __shared__ __align__(8)  unsigned long long mbar[2];

    const int tid  = threadIdx.x;
    const int lane = tid & 31;
    const int ty   = tid >> 5;            // 0..3
    const int jc   = lane * 4;
    const int wu0  = blockIdx.x * T_TILES;

    if (tid == 0) {
        asm volatile("mbarrier.init.shared::cta.b64 [%0], 1;" :: "r"(s2u(&mbar[0])) : "memory");
        asm volatile("mbarrier.init.shared::cta.b64 [%0], 1;" :: "r"(s2u(&mbar[1])) : "memory");
    }
    __syncthreads();

    // Issue TMA bulk load for tile t into s_in[t&1]; zero-fill clipped halo rows.
    auto issue_load = [&](int t) {
        const int wu   = wu0 + t;
        const int chan = wu >> 4;          // b*C + c
        const int rb   = wu & 15;          // 0..15
        const int r0   = rb * RPB;
        const int lo_row = (r0 == 0) ? 0 : r0 - 1;
        const int hi_row = (r0 + RPB == H_IN) ? H_IN : r0 + RPB + 1;  // exclusive
        const uint32_t nbytes = (uint32_t)(hi_row - lo_row) * (W_IN * 4);
        const int b = t & 1;
        if (tid == 0) {
            asm volatile("mbarrier.arrive.expect_tx.shared::cta.b64 _, [%0], %1;"
                         :: "r"(s2u(&mbar[b])), "r"(nbytes) : "memory");
            const uint32_t dst = s2u(&s_in[b][0]) + (uint32_t)(lo_row - (r0 - 1)) * (W_IN * 4);
            asm volatile("cp.async.bulk.shared::cta.global.mbarrier::complete_tx::bytes "
                         "[%0], [%1], %2, [%3];"
                         :: "r"(dst),
                            "l"(x + (size_t)chan * (H_IN * W_IN) + (size_t)lo_row * W_IN),
                            "r"(nbytes), "r"(s2u(&mbar[b])) : "memory");
        }
        if (r0 == 0 && tid < 32)
            *(float4*)&s_in[b][tid * 4] = make_float4(0.f, 0.f, 0.f, 0.f);
        if (r0 + RPB == H_IN && tid < 32)
            *(float4*)&s_in[b][(IN_TROWS - 1) * W_IN + tid * 4] = make_float4(0.f, 0.f, 0.f, 0.f);
    };

    issue_load(0);

    #pragma unroll 1
    for (int t = 0; t < T_TILES; t++) {
        const int b = t & 1;
        if (t + 1 < T_TILES) issue_load(t + 1);

        // Wait for load of tile t (parity (t>>1)&1).
        {
            const uint32_t mb = s2u(&mbar[b]);
            const uint32_t ph = (t >> 1) & 1;
            uint32_t done;
            asm volatile(
                "{\n\t.reg .pred p;\n\t"
                "mbarrier.try_wait.parity.acquire.cta.shared::cta.b64 p, [%1], %2;\n\t"
                "selp.b32 %0, 1, 0, p;\n\t}"
                : "=r"(done) : "r"(mb), "r"(ph) : "memory");
            if (!done) {
                asm volatile(
                    "{\n\t.reg .pred P1;\n\t"
                    "W_%=:\n\t"
                    "mbarrier.try_wait.parity.acquire.cta.shared::cta.b64 P1, [%0], %1, 0x989680;\n\t"
                    "@P1 bra.uni D_%=;\n\t"
                    "bra.uni W_%=;\n\t"
                    "D_%=:\n\t}"
                    :: "r"(mb), "r"(ph) : "memory");
            }
        }
        // Backpressure: s_out[b] must be free (store t-2 complete).
        if (tid == 0)
            asm volatile("cp.async.bulk.wait_group 1;" ::: "memory");
        __syncthreads();

        // ---- compute tile t: thread (lane, ty) -> input rows 2ty, 2ty+1 ----
        const float4 m0 = *(const float4*)&s_in[b][(2*ty    ) * W_IN + jc];
        const float4 m1 = *(const float4*)&s_in[b][(2*ty + 1) * W_IN + jc];
        const float4 m2 = *(const float4*)&s_in[b][(2*ty + 2) * W_IN + jc];
        const float4 m3 = *(const float4*)&s_in[b][(2*ty + 3) * W_IN + jc];

        const float4 e0 = blend(0.25f, m0, 0.75f, m1);
        const float4 o0 = blend(0.75f, m1, 0.25f, m2);
        const float4 e1 = blend(0.25f, m1, 0.75f, m2);
        const float4 o1 = blend(0.75f, m2, 0.25f, m3);

        float* q = &s_out[b][(4 * ty) * W_OUT + 2 * jc];
        float4 lov, hiv;
        hup(e0, lane, lov, hiv);
        *(float4*)(q)                 = lov;  *(float4*)(q + 4)             = hiv;
        hup(o0, lane, lov, hiv);
        *(float4*)(q + W_OUT)         = lov;  *(float4*)(q + W_OUT + 4)     = hiv;
        hup(e1, lane, lov, hiv);
        *(float4*)(q + 2 * W_OUT)     = lov;  *(float4*)(q + 2 * W_OUT + 4) = hiv;
        hup(o1, lane, lov, hiv);
        *(float4*)(q + 3 * W_OUT)     = lov;  *(float4*)(q + 3 * W_OUT + 4) = hiv;

        __syncthreads();   // s_out[b] complete; s_in[b] fully consumed

        if (tid == 0) {
            const int wu   = wu0 + t;
            const int chan = wu >> 4;
            const int r0   = (wu & 15) * RPB;
            float* op = out + (size_t)chan * (2 * H_IN * W_OUT) + (size_t)(2 * r0) * W_OUT;
            asm volatile("fence.proxy.async.shared::cta;" ::: "memory");
            asm volatile("cp.async.bulk.global.shared::cta.bulk_group [%0], [%1], %2;"
                         :: "l"(op), "r"(s2u(&s_out[b][0])),
                            "r"((uint32_t)(2 * RPB * W_OUT * 4)) : "memory");
            asm volatile("cp.async.bulk.commit_group;" ::: "memory");
        }
    }

    // Drain remaining stores before smem is released.
    if (tid == 0)
        asm volatile("cp.async.bulk.wait_group 0;" ::: "memory");
}

extern "C" void kernel_launch(void* const* d_in, const int* in_sizes, int n_in,
                              void* d_out, int out_size) {
    const float* x = (const float*)d_in[0];
    float* out = (float*)d_out;
    // total work units = 8*128*16 = 16384; T_TILES per block
    upsample2x_fir_kernel<<<16384 / T_TILES, NTHREADS>>>(x, out);
}

// round 16
// speedup vs baseline: 1.2662x; 1.2662x over previous
#include <cuda_runtime.h>
#include <cstdint>

// 2x FIR upsample, depthwise separable [1,3,3,1]/4 per axis (factor=2 gain).
//   out[2i]   = 0.25*x[i-1] + 0.75*x[i]
//   out[2i+1] = 0.75*x[i]   + 0.25*x[i+1]
// Input (8,128,128,128) f32 -> Output (8,128,256,256) f32.
//
// Small-tile TMA in/out workers for maximum per-SM pipeline concurrency:
//   RPB=4 input rows/block, 128 threads, ~11KB smem -> up to 16 blocks/SM,
//   each an independent TMA-load -> compute -> TMA-store pipeline.

#define H_IN 128
#define W_IN 128
#define W_OUT 256
#define RPB 4                     // input rows per block
#define IN_TROWS (RPB + 2)        // staged rows r0-1 .. r0+4
#define NTHREADS 128

__device__ __forceinline__ uint32_t s2u(const void* p) {
    return (uint32_t)__cvta_generic_to_shared(p);
}

__device__ __forceinline__ float4 blend(float wa, float4 a, float wb, float4 b) {
    return make_float4(wa*a.x + wb*b.x, wa*a.y + wb*b.y,
                       wa*a.z + wb*b.z, wa*a.w + wb*b.w);
}

// Horizontal 2x upsample: lane l holds cols 4l..4l+3; halo via shfl
// (zero at edges: W=128=32*4 spans the warp exactly).
__device__ __forceinline__ void hup(float4 v, int lane, float4& lo, float4& hi) {
    float left  = __shfl_up_sync(0xFFFFFFFFu, v.w, 1);
    float right = __shfl_down_sync(0xFFFFFFFFu, v.x, 1);
    if (lane == 0)  left  = 0.f;
    if (lane == 31) right = 0.f;
    lo.x = 0.25f * left + 0.75f * v.x;
    lo.y = 0.75f * v.x  + 0.25f * v.y;
    lo.z = 0.25f * v.x  + 0.75f * v.y;
    lo.w = 0.75f * v.y  + 0.25f * v.z;
    hi.x = 0.25f * v.y  + 0.75f * v.z;
    hi.y = 0.75f * v.z  + 0.25f * v.w;
    hi.z = 0.25f * v.z  + 0.75f * v.w;
    hi.w = 0.75f * v.w  + 0.25f * right;
}

__global__ __launch_bounds__(NTHREADS)
void upsample2x_fir_kernel(const float* __restrict__ x, float* __restrict__ out) {
    __shared__ __align__(16) float s_in[IN_TROWS * W_IN];     // 3072 B
    __shared__ __align__(16) float s_out[2 * RPB * W_OUT];    // 8192 B
    __shared__ __align__(8)  unsigned long long mbar;

    const int tid  = threadIdx.x;
    const int wu   = blockIdx.x;                              // 0..32767
    const int chan = wu >> 5;                                 // b*C + c
    const int rb   = wu & 31;                                 // 0..31
    const float* xp = x   + (size_t)chan * (H_IN * W_IN);
    float*       op = out + (size_t)chan * (2 * H_IN * W_OUT);

    const int r0 = rb * RPB;
    const int lo_row = (r0 == 0) ? 0 : r0 - 1;
    const int hi_row = (r0 + RPB == H_IN) ? H_IN : r0 + RPB + 1;  // exclusive
    const uint32_t nbytes = (uint32_t)(hi_row - lo_row) * (W_IN * 4);

    if (tid == 0) {
        asm volatile("mbarrier.init.shared::cta.b64 [%0], 1;"
                     :: "r"(s2u(&mbar)) : "memory");
    }
    __syncthreads();   // mbar init visible before any wait

    if (tid == 0) {
        asm volatile("mbarrier.arrive.expect_tx.shared::cta.b64 _, [%0], %1;"
                     :: "r"(s2u(&mbar)), "r"(nbytes) : "memory");
        const uint32_t dst = s2u(s_in) + (uint32_t)(lo_row - (r0 - 1)) * (W_IN * 4);
        asm volatile("cp.async.bulk.shared::cta.global.mbarrier::complete_tx::bytes "
                     "[%0], [%1], %2, [%3];"
                     :: "r"(dst), "l"(xp + (size_t)lo_row * W_IN),
                        "r"(nbytes), "r"(s2u(&mbar)) : "memory");
    }

    // Zero clipped halo rows (regions the bulk load does not touch).
    if (r0 == 0 && tid < 32)
        *(float4*)&s_in[tid * 4] = make_float4(0.f, 0.f, 0.f, 0.f);
    if (r0 + RPB == H_IN && tid < 32)
        *(float4*)&s_in[(IN_TROWS - 1) * W_IN + tid * 4] = make_float4(0.f, 0.f, 0.f, 0.f);

    // Wait for bulk load (parity 0).
    {
        const uint32_t mb = s2u(&mbar);
        uint32_t done;
        asm volatile(
            "{\n\t.reg .pred p;\n\t"
            "mbarrier.try_wait.parity.acquire.cta.shared::cta.b64 p, [%1], 0;\n\t"
            "selp.b32 %0, 1, 0, p;\n\t}"
            : "=r"(done) : "r"(mb) : "memory");
        if (!done) {
            asm volatile(
                "{\n\t.reg .pred P1;\n\t"
                "W_%=:\n\t"
                "mbarrier.try_wait.parity.acquire.cta.shared::cta.b64 P1, [%0], 0, 0x989680;\n\t"
                "@P1 bra.uni D_%=;\n\t"
                "bra.uni W_%=;\n\t"
                "D_%=:\n\t}"
                :: "r"(mb) : "memory");
        }
    }
    __syncthreads();   // orders the zero-fill STS too

    // ---- compute: warp w handles input row r0+w (-> 2 output rows) ----
    const int lane = tid & 31;
    const int w    = tid >> 5;            // 0..3
    const int jc   = lane * 4;            // col base

    // s_in row s holds input row r0-1+s.
    const float4 m0 = *(const float4*)&s_in[(w    ) * W_IN + jc];   // row-1
    const float4 m1 = *(const float4*)&s_in[(w + 1) * W_IN + jc];   // row
    const float4 m2 = *(const float4*)&s_in[(w + 2) * W_IN + jc];   // row+1

    const float4 ev = blend(0.25f, m0, 0.75f, m1);   // out tile row 2w
    const float4 od = blend(0.75f, m1, 0.25f, m2);   // out tile row 2w+1

    float* q = &s_out[(2 * w) * W_OUT + 2 * jc];
    float4 lov, hiv;
    hup(ev, lane, lov, hiv);
    *(float4*)(q)             = lov;  *(float4*)(q + 4)         = hiv;
    hup(od, lane, lov, hiv);
    *(float4*)(q + W_OUT)     = lov;  *(float4*)(q + W_OUT + 4) = hiv;

    __syncthreads();

    // ---- bulk store: 8 contiguous output rows = 8 KB ----
    if (tid == 0) {
        asm volatile("fence.proxy.async.shared::cta;" ::: "memory");
        asm volatile("cp.async.bulk.global.shared::cta.bulk_group [%0], [%1], %2;"
                     :: "l"(op + (size_t)(2 * r0) * W_OUT), "r"(s2u(s_out)),
                        "r"((uint32_t)(2 * RPB * W_OUT * 4)) : "memory");
        asm volatile("cp.async.bulk.commit_group;" ::: "memory");
        asm volatile("cp.async.bulk.wait_group 0;" ::: "memory");
    }
}

extern "C" void kernel_launch(void* const* d_in, const int* in_sizes, int n_in,
                              void* d_out, int out_size) {
    const float* x = (const float*)d_in[0];
    float* out = (float*)d_out;
    // work units = 8*128 channels * 32 row-blocks = 32768
    upsample2x_fir_kernel<<<32768, NTHREADS>>>(x, out);
}